// round 14
// baseline (speedup 1.0000x reference)
#include <cuda_runtime.h>
#include <cuda.h>
#include <cuda_bf16.h>
#include <cstdint>
#include <cstddef>

// ---------------- problem constants ----------------
#define BATCH   4096
#define UNITS   1024
#define TSTEPS  128
#define BM      256            // batch rows per tile
#define BN      128            // z-cols per tile = 32 units * 4 gates
#define KC      32             // K fp32 elements per chunk (128B rows, SW128)
#define NKC     32             // chunks over K=1024
#define NMT     16             // m tiles (4096/256)
#define NNT     32             // n tiles
#define ROWB    128            // smem row bytes
#define PL_A    (256 * ROWB)   // 32768 B (A plane: 256 rows)
#define PL_B    (128 * ROWB)   // 16384 B (B plane: 128 rows)
#define O_A     0
#define O_B     (PL_A)
#define STAGE   (PL_A + PL_B)  // 49152 B
#define NSTG    3
#define SMEM_DYN (NSTG * STAGE)   // 147456 B (1 CTA/SM)
#define HN      (4096UL * 1024UL)

// ---------------- device-global state ----------------
__device__ float g_h[2][HN];        // hidden state, tf32-rounded fp32 (ping/pong)
__device__ float g_W[HN];           // permuted W, tf32-rounded fp32: [n=4u+g][k]
__device__ float g_c[HN];           // cell state fp32, in place
__device__ float g_kp[4 * UNITS];   // permuted input kernel
__device__ float g_bp[4 * UNITS];   // permuted bias
__device__ float g_x[BATCH];        // autoregressive feedback (pred of prev step)
__device__ int   g_cnt[TSTEPS][NMT];      // per (step, m-block) tile arrivals
__device__ float g_xpart[BATCH][64];      // pred dot partials

// ---------------- PTX helpers ----------------
__device__ __forceinline__ uint32_t smem_u32(const void* p) {
    uint32_t a;
    asm("{ .reg .u64 t; cvta.to.shared.u64 t, %1; cvt.u32.u64 %0, t; }" : "=r"(a) : "l"(p));
    return a;
}
__device__ __forceinline__ void mbar_init(uint32_t a, uint32_t c) {
    asm volatile("mbarrier.init.shared.b64 [%0], %1;" :: "r"(a), "r"(c) : "memory");
}
__device__ __forceinline__ void mbar_expect(uint32_t a, uint32_t bytes) {
    asm volatile("mbarrier.arrive.expect_tx.shared.b64 _, [%0], %1;" :: "r"(a), "r"(bytes) : "memory");
}
__device__ __forceinline__ void mbar_wait(uint32_t a, uint32_t ph) {
    asm volatile(
        "{\n\t.reg .pred P;\n"
        "WL%=:\n\t"
        "mbarrier.try_wait.parity.acquire.cta.shared::cta.b64 P, [%0], %1, 0x989680;\n\t"
        "@P bra.uni WD%=;\n\t"
        "bra.uni WL%=;\n"
        "WD%=:\n\t}"
        :: "r"(a), "r"(ph) : "memory");
}
__device__ __forceinline__ void tma3d(uint32_t dst, const CUtensorMap* m, int x, int y, int z, uint32_t bar) {
    asm volatile(
        "cp.async.bulk.tensor.3d.shared::cta.global.tile.mbarrier::complete_tx::bytes "
        "[%0], [%1, {%2, %3, %4}], [%5];"
        :: "r"(dst), "l"(m), "r"(x), "r"(y), "r"(z), "r"(bar) : "memory");
}
__device__ __forceinline__ void tma2d(uint32_t dst, const CUtensorMap* m, int x, int y, uint32_t bar) {
    asm volatile(
        "cp.async.bulk.tensor.2d.shared::cta.global.tile.mbarrier::complete_tx::bytes "
        "[%0], [%1, {%2, %3}], [%4];"
        :: "r"(dst), "l"(m), "r"(x), "r"(y), "r"(bar) : "memory");
}
__device__ __forceinline__ void ldsm_x4(uint32_t addr, uint32_t* r) {
    asm volatile("ldmatrix.sync.aligned.m8n8.x4.shared.b16 {%0,%1,%2,%3}, [%4];"
                 : "=r"(r[0]), "=r"(r[1]), "=r"(r[2]), "=r"(r[3]) : "r"(addr));
}
__device__ __forceinline__ void mma_tf32(float* d, const uint32_t* a, const uint32_t* b) {
    asm volatile(
        "mma.sync.aligned.m16n8k8.row.col.f32.tf32.tf32.f32 "
        "{%0,%1,%2,%3}, {%4,%5,%6,%7}, {%8,%9}, {%0,%1,%2,%3};"
        : "+f"(d[0]), "+f"(d[1]), "+f"(d[2]), "+f"(d[3])
        : "r"(a[0]), "r"(a[1]), "r"(a[2]), "r"(a[3]), "r"(b[0]), "r"(b[1]));
}
__device__ __forceinline__ float tf32r(float v) {
    uint32_t u;
    asm("cvt.rna.tf32.f32 %0, %1;" : "=r"(u) : "f"(v));
    return __uint_as_float(u);
}
__device__ __forceinline__ float sigf(float x) {
    return __fdividef(1.0f, 1.0f + __expf(-x));
}
__device__ __forceinline__ float tanhf_(float x) {
    return __fdividef(2.0f, 1.0f + __expf(-2.0f * x)) - 1.0f;
}
__device__ __forceinline__ uint32_t swz128(uint32_t off) {
    return off ^ ((off >> 3) & 0x70);
}

// ---------------- prep kernels ----------------
__global__ void prep_w_kernel(const float* __restrict__ W) {
    int u = blockIdx.x * 32 + threadIdx.x;
    int k = blockIdx.y * 8 + threadIdx.y;
    int g = blockIdx.z;
    float v = W[(size_t)k * 4096 + g * 1024 + u];
    g_W[((size_t)(4 * u + g)) * 1024 + k] = tf32r(v);
}

__global__ void prep_small_kernel(const float* __restrict__ kern, const float* __restrict__ bias) {
    int idx = blockIdx.x * 256 + threadIdx.x;   // 0..4095
    int g = idx & 3, u = idx >> 2;
    int c = g * 1024 + u;
    g_kp[idx] = kern[c];
    g_bp[idx] = bias[c];
    if (idx < TSTEPS * NMT) ((int*)g_cnt)[idx] = 0;
}

__global__ void init_hc_kernel(const float* __restrict__ feat) {
    size_t idx = (size_t)blockIdx.x * 1024 + threadIdx.x;
    int b = blockIdx.x, u = threadIdx.x;
    float v = feat[(size_t)b * 512 + (u & 511)];
    g_h[0][idx] = tf32r(v);
    g_c[idx] = v;
}

// ---------------- fused LSTM step (tf32, 256x128 tile, 8 warps x 64x64) ----------------
__global__ void __launch_bounds__(256, 1)
step_kernel(const __grid_constant__ CUtensorMap mA,
            const __grid_constant__ CUtensorMap mB,
            const float* __restrict__ dw,
            const float* __restrict__ db,
            float* __restrict__ out,
            int t)
{
    extern __shared__ __align__(1024) char sm[];
    __shared__ uint64_t barmem[NSTG];
    __shared__ int sflag;

    const int tid = threadIdx.x;
    const int w = tid >> 5, l = tid & 31;
    const int src = t & 1;
    const int dst = src ^ 1;
    const int mt = blockIdx.x & 15, nt = blockIdx.x >> 4;
    const int m0 = mt << 8;      // batch row base (256 rows)
    const int n0 = nt << 7;      // z col base (128 cols)
    const int u0 = nt << 5;      // unit base (32 units)

    const uint32_t sb = smem_u32(sm);
    uint32_t bars[NSTG];
    #pragma unroll
    for (int s = 0; s < NSTG; s++) bars[s] = smem_u32(&barmem[s]);

    if (tid == 0) {
        #pragma unroll
        for (int s = 0; s < NSTG; s++) mbar_init(bars[s], 1);
        asm volatile("fence.proxy.async.shared::cta;" ::: "memory");
    }
    __syncthreads();

    // producer: issue chunk kc into stage kc%3 (tid 0 only)
    auto issue = [&](int kc) {
        int s = kc % NSTG;
        uint32_t st = sb + (uint32_t)s * STAGE;
        int k0 = kc * KC;
        mbar_expect(bars[s], STAGE);
        tma3d(st + O_A, &mA, k0, m0, src, bars[s]);
        tma2d(st + O_B, &mB, k0, n0, bars[s]);
    };
    if (tid == 0) { issue(0); issue(1); issue(2); }

    // warp tiling: 4 (m) x 2 (n); warp tile 64x64
    const int m_off = (w & 3) * 64;
    const int n_off = (w >> 2) * 64;
    const int par = l & 1;

    float acc[4][8][4];
    #pragma unroll
    for (int im = 0; im < 4; im++)
        #pragma unroll
        for (int jn = 0; jn < 8; jn++)
            #pragma unroll
            for (int q = 0; q < 4; q++) acc[im][jn][q] = 0.0f;

    // ldsm addresses (tf32 fragments via b16 ldmatrix on fp32 data; SW128 rows)
    auto a_addr = [&](uint32_t plane, int im, int ks) -> uint32_t {
        int row = m_off + im * 16 + (l & 7) + ((l >> 3) & 1) * 8;
        uint32_t byte = ks * 32 + ((l >> 4) << 4);
        return plane + swz128((uint32_t)row * ROWB + byte);
    };
    auto b_addr = [&](uint32_t plane, int jn2, int ks) -> uint32_t {
        int row = n_off + jn2 * 16 + (l & 7) + ((l >> 4) << 3);
        uint32_t byte = ks * 32 + (((l >> 3) & 1) << 4);
        return plane + swz128((uint32_t)row * ROWB + byte);
    };

    // ---- mainloop: 3-stage TMA pipeline, one sync per chunk ----
    uint32_t wcnt[NSTG] = {0, 0, 0};
    for (int kc = 0; kc < NKC; kc++) {
        const int s = kc % NSTG;
        const uint32_t so = sb + (uint32_t)s * STAGE;
        mbar_wait(bars[s], wcnt[s] & 1);
        wcnt[s]++;
        #pragma unroll
        for (int ks = 0; ks < 4; ks++) {
            uint32_t af[4][4], bf2[4][4];
            #pragma unroll
            for (int im = 0; im < 4; im++) ldsm_x4(a_addr(so + O_A, im, ks), af[im]);
            #pragma unroll
            for (int jn2 = 0; jn2 < 4; jn2++) ldsm_x4(b_addr(so + O_B, jn2, ks), bf2[jn2]);
            #pragma unroll
            for (int im = 0; im < 4; im++)
                #pragma unroll
                for (int jn2 = 0; jn2 < 4; jn2++) {
                    mma_tf32(acc[im][jn2 * 2 + 0], af[im], &bf2[jn2][0]);
                    mma_tf32(acc[im][jn2 * 2 + 1], af[im], &bf2[jn2][2]);
                }
        }
        __syncthreads();
        if (tid == 0 && kc + NSTG < NKC) issue(kc + NSTG);
    }

    // ---- fragment-direct epilogue + pred dot partials ----
    {
        float kpv[8][2], bpv[8][2], dwv[8];
        const int myq = (l & 3) >> 1;
        #pragma unroll
        for (int jn = 0; jn < 8; jn++) {
            #pragma unroll
            for (int q = 0; q < 2; q++) {
                int n = n0 + n_off + jn * 8 + (l & 3) * 2 + q;
                kpv[jn][q] = g_kp[n];
                bpv[jn][q] = g_bp[n];
            }
            dwv[jn] = dw[u0 + (n_off >> 2) + jn * 2 + myq];
        }
        #pragma unroll
        for (int im = 0; im < 4; im++) {
            #pragma unroll
            for (int half = 0; half < 2; half++) {
                int row = m0 + m_off + im * 16 + (l >> 2) + half * 8;
                float xr = (t == 0) ? 0.0f : g_x[row];
                float s = 0.0f;
                #pragma unroll
                for (int jn = 0; jn < 8; jn++) {
                    float zA = acc[im][jn][half * 2 + 0] + xr * kpv[jn][0] + bpv[jn][0];
                    float zB = acc[im][jn][half * 2 + 1] + xr * kpv[jn][1] + bpv[jn][1];
                    // even lane: i = sig(zA), f = sig(zB); odd lane: g = tanh(zA), o = sig(zB)
                    float vA = par ? tanhf_(zA) : sigf(zA);
                    float vB = sigf(zB);
                    int u = u0 + ((n_off + jn * 8 + (l & 3) * 2) >> 2);
                    size_t gi = (size_t)row * 1024 + u;
                    float gx = __shfl_xor_sync(0xFFFFFFFFu, vA, 1);  // even receives g
                    float cn = 0.0f;
                    if (!par) {
                        float co = g_c[gi];
                        cn = vB * co + vA * gx;       // f*c + i*g
                        g_c[gi] = cn;
                    }
                    float cnx = __shfl_xor_sync(0xFFFFFFFFu, cn, 1); // odd receives c_new
                    if (par) {
                        float hn = vB * tanhf_(cnx);  // o * tanh(c_new)
                        g_h[dst][gi] = tf32r(hn);
                        s += hn * dwv[jn];
                    }
                }
                s += __shfl_xor_sync(0xFFFFFFFFu, s, 2);
                if ((l & 3) == 1)
                    g_xpart[row][nt * 2 + (n_off >> 6)] = s;
            }
        }
    }

    // ---- arrive; last tile of this m-block finishes pred + feedback ----
    __syncthreads();
    if (tid == 0) {
        __threadfence();
        int old = atomicAdd(&g_cnt[t][mt], 1);
        sflag = (old == NNT - 1) ? 1 : 0;
    }
    __syncthreads();
    if (sflag) {
        __threadfence();   // observe all tiles' xpart writes
        float dbv = db[0];
        int row = m0 + tid;     // 256 threads -> 256 rows
        const float4* xp4 = (const float4*)&g_xpart[row][0];
        float p = 0.0f;
        #pragma unroll
        for (int i = 0; i < 16; i++) {
            float4 v = xp4[i];
            p += v.x + v.y + v.z + v.w;
        }
        p += dbv;
        out[(size_t)row * TSTEPS + t] = p;
        g_x[row] = p;
    }
}

// ---------------- host side ----------------
typedef CUresult (*PFN_tmap)(CUtensorMap*, CUtensorMapDataType, cuuint32_t, void*,
    const cuuint64_t*, const cuuint64_t*, const cuuint32_t*, const cuuint32_t*,
    CUtensorMapInterleave, CUtensorMapSwizzle, CUtensorMapL2promotion, CUtensorMapFloatOOBfill);

static void enc2d(PFN_tmap fn, CUtensorMap* m, void* base) {
    cuuint64_t dims[2]    = { 1024, 4096 };
    cuuint64_t strides[1] = { 4096 };          // row = 1024 fp32 = 4096 B
    cuuint32_t box[2]     = { KC, 128 };       // 32 fp32 = 128 B rows
    cuuint32_t es[2]      = { 1, 1 };
    fn(m, CU_TENSOR_MAP_DATA_TYPE_FLOAT32, 2, base, dims, strides, box, es,
       CU_TENSOR_MAP_INTERLEAVE_NONE, CU_TENSOR_MAP_SWIZZLE_128B,
       CU_TENSOR_MAP_L2_PROMOTION_L2_128B, CU_TENSOR_MAP_FLOAT_OOB_FILL_NONE);
}
static void enc3d(PFN_tmap fn, CUtensorMap* m, void* base) {
    cuuint64_t dims[3]    = { 1024, 4096, 2 };
    cuuint64_t strides[2] = { 4096, 4096ULL * 4096ULL };
    cuuint32_t box[3]     = { KC, 256, 1 };    // 256-row A box
    cuuint32_t es[3]      = { 1, 1, 1 };
    fn(m, CU_TENSOR_MAP_DATA_TYPE_FLOAT32, 3, base, dims, strides, box, es,
       CU_TENSOR_MAP_INTERLEAVE_NONE, CU_TENSOR_MAP_SWIZZLE_128B,
       CU_TENSOR_MAP_L2_PROMOTION_L2_128B, CU_TENSOR_MAP_FLOAT_OOB_FILL_NONE);
}

extern "C" void kernel_launch(void* const* d_in, const int* in_sizes, int n_in,
                              void* d_out, int out_size) {
    const float* features = (const float*)d_in[0];
    const float* kern     = (const float*)d_in[1];
    const float* W        = (const float*)d_in[2];
    const float* bias     = (const float*)d_in[3];
    const float* dw       = (const float*)d_in[4];
    const float* db       = (const float*)d_in[5];
    float* out = (float*)d_out;

    PFN_tmap enc = nullptr;
    {
        cudaDriverEntryPointQueryResult qr;
        void* fp = nullptr;
        cudaGetDriverEntryPointByVersion("cuTensorMapEncodeTiled", &fp, 12000,
                                         cudaEnableDefault, &qr);
        enc = (PFN_tmap)fp;
    }

    void *pH = nullptr, *pW = nullptr;
    cudaGetSymbolAddress(&pH, g_h);
    cudaGetSymbolAddress(&pW, g_W);

    CUtensorMap mA, mB;
    enc3d(enc, &mA, pH);
    enc2d(enc, &mB, pW);

    cudaFuncSetAttribute(step_kernel, cudaFuncAttributeMaxDynamicSharedMemorySize, SMEM_DYN);

    prep_w_kernel<<<dim3(32, 128, 4), dim3(32, 8)>>>(W);
    prep_small_kernel<<<16, 256>>>(kern, bias);
    init_hc_kernel<<<4096, 1024>>>(features);

    for (int t = 0; t < TSTEPS; t++) {
        step_kernel<<<NMT * NNT, 256, SMEM_DYN>>>(mA, mB, dw, db, out, t);
    }
}

// round 15
// speedup vs baseline: 2.0211x; 2.0211x over previous
#include <cuda_runtime.h>
#include <cuda.h>
#include <cuda_fp16.h>
#include <cstdint>
#include <cstddef>

// ---------------- problem constants ----------------
#define BATCH   4096
#define UNITS   1024
#define TSTEPS  128
#define BM      128            // batch rows per tile
#define BN      128            // z-cols per tile = 32 units * 4 gates
#define KC      64             // K fp16 elements per chunk (128B rows, SW128)
#define NKC     16             // chunks over K=1024
#define NMT     32             // m tiles
#define NNT     32             // n tiles
#define ROWB    128            // smem row bytes
#define PL      (128 * ROWB)   // 16384 B per plane (A / B)
#define O_A     0
#define O_B     (PL)
#define STAGE   (2 * PL)       // 32768 B
#define NSTG    3
#define SMEM_DYN (NSTG * STAGE)   // 98304 B (2 CTAs/SM)
#define HN      (4096UL * 1024UL)

// ---------------- device-global state ----------------
__device__ __half g_h[2][HN];       // hidden state fp16 (ping/pong)
__device__ __half g_W[HN];          // permuted W fp16: [n=4u+g][k]
__device__ float  g_c[HN];          // cell state fp32, in place
__device__ float  g_kp[4 * UNITS];  // permuted input kernel
__device__ float  g_bp[4 * UNITS];  // permuted bias
__device__ float  g_x[BATCH];       // autoregressive feedback (pred of prev step)
__device__ int    g_cnt[TSTEPS][NMT];     // per (step, m-block) tile arrivals
__device__ float  g_xpart[BATCH][64];     // pred dot partials

// ---------------- PTX helpers ----------------
__device__ __forceinline__ uint32_t smem_u32(const void* p) {
    uint32_t a;
    asm("{ .reg .u64 t; cvta.to.shared.u64 t, %1; cvt.u32.u64 %0, t; }" : "=r"(a) : "l"(p));
    return a;
}
__device__ __forceinline__ void mbar_init(uint32_t a, uint32_t c) {
    asm volatile("mbarrier.init.shared.b64 [%0], %1;" :: "r"(a), "r"(c) : "memory");
}
__device__ __forceinline__ void mbar_expect(uint32_t a, uint32_t bytes) {
    asm volatile("mbarrier.arrive.expect_tx.shared.b64 _, [%0], %1;" :: "r"(a), "r"(bytes) : "memory");
}
__device__ __forceinline__ void mbar_wait(uint32_t a, uint32_t ph) {
    asm volatile(
        "{\n\t.reg .pred P;\n"
        "WL%=:\n\t"
        "mbarrier.try_wait.parity.acquire.cta.shared::cta.b64 P, [%0], %1, 0x989680;\n\t"
        "@P bra.uni WD%=;\n\t"
        "bra.uni WL%=;\n"
        "WD%=:\n\t}"
        :: "r"(a), "r"(ph) : "memory");
}
__device__ __forceinline__ void tma3d(uint32_t dst, const CUtensorMap* m, int x, int y, int z, uint32_t bar) {
    asm volatile(
        "cp.async.bulk.tensor.3d.shared::cta.global.tile.mbarrier::complete_tx::bytes "
        "[%0], [%1, {%2, %3, %4}], [%5];"
        :: "r"(dst), "l"(m), "r"(x), "r"(y), "r"(z), "r"(bar) : "memory");
}
__device__ __forceinline__ void tma2d(uint32_t dst, const CUtensorMap* m, int x, int y, uint32_t bar) {
    asm volatile(
        "cp.async.bulk.tensor.2d.shared::cta.global.tile.mbarrier::complete_tx::bytes "
        "[%0], [%1, {%2, %3}], [%4];"
        :: "r"(dst), "l"(m), "r"(x), "r"(y), "r"(bar) : "memory");
}
__device__ __forceinline__ void ldsm_x4(uint32_t addr, uint32_t* r) {
    asm volatile("ldmatrix.sync.aligned.m8n8.x4.shared.b16 {%0,%1,%2,%3}, [%4];"
                 : "=r"(r[0]), "=r"(r[1]), "=r"(r[2]), "=r"(r[3]) : "r"(addr));
}
__device__ __forceinline__ void mma_f16(float* d, const uint32_t* a, const uint32_t* b) {
    asm volatile(
        "mma.sync.aligned.m16n8k16.row.col.f32.f16.f16.f32 "
        "{%0,%1,%2,%3}, {%4,%5,%6,%7}, {%8,%9}, {%0,%1,%2,%3};"
        : "+f"(d[0]), "+f"(d[1]), "+f"(d[2]), "+f"(d[3])
        : "r"(a[0]), "r"(a[1]), "r"(a[2]), "r"(a[3]), "r"(b[0]), "r"(b[1]));
}
__device__ __forceinline__ float sigf(float x) {
    return __fdividef(1.0f, 1.0f + __expf(-x));
}
__device__ __forceinline__ float tanhf_(float x) {
    return __fdividef(2.0f, 1.0f + __expf(-2.0f * x)) - 1.0f;
}
__device__ __forceinline__ uint32_t swz128(uint32_t off) {
    return off ^ ((off >> 3) & 0x70);
}

// ---------------- prep kernels ----------------
__global__ void prep_w_kernel(const float* __restrict__ W) {
    int u = blockIdx.x * 32 + threadIdx.x;
    int k = blockIdx.y * 8 + threadIdx.y;
    int g = blockIdx.z;
    float v = W[(size_t)k * 4096 + g * 1024 + u];
    g_W[((size_t)(4 * u + g)) * 1024 + k] = __float2half_rn(v);
}

__global__ void prep_small_kernel(const float* __restrict__ kern, const float* __restrict__ bias) {
    int idx = blockIdx.x * 256 + threadIdx.x;   // 0..4095
    int g = idx & 3, u = idx >> 2;
    int c = g * 1024 + u;
    g_kp[idx] = kern[c];
    g_bp[idx] = bias[c];
    if (idx < TSTEPS * NMT) ((int*)g_cnt)[idx] = 0;
}

__global__ void init_hc_kernel(const float* __restrict__ feat) {
    size_t idx = (size_t)blockIdx.x * 1024 + threadIdx.x;
    int b = blockIdx.x, u = threadIdx.x;
    float v = feat[(size_t)b * 512 + (u & 511)];
    g_h[0][idx] = __float2half_rn(v);
    g_c[idx] = v;
}

// ---------------- fused LSTM step (fp16 single-pass, 8 warps, fused collect) ----------------
__global__ void __launch_bounds__(256, 2)
step_kernel(const __grid_constant__ CUtensorMap mA,
            const __grid_constant__ CUtensorMap mB,
            const float* __restrict__ dw,
            const float* __restrict__ db,
            float* __restrict__ out,
            int t)
{
    extern __shared__ __align__(1024) char sm[];
    __shared__ uint64_t barmem[NSTG];
    __shared__ int sflag;

    const int tid = threadIdx.x;
    const int w = tid >> 5, l = tid & 31;
    const int src = t & 1;
    const int dst = src ^ 1;
    const int mt = blockIdx.x & 31, nt = blockIdx.x >> 5;
    const int m0 = mt << 7;      // batch row base
    const int n0 = nt << 7;      // z col base (128 cols)
    const int u0 = nt << 5;      // unit base (32 units)

    const uint32_t sb = smem_u32(sm);
    uint32_t bars[NSTG];
    #pragma unroll
    for (int s = 0; s < NSTG; s++) bars[s] = smem_u32(&barmem[s]);

    if (tid == 0) {
        #pragma unroll
        for (int s = 0; s < NSTG; s++) mbar_init(bars[s], 1);
        asm volatile("fence.proxy.async.shared::cta;" ::: "memory");
    }
    __syncthreads();

    // producer: issue chunk kc into stage kc%3 (tid 0 only)
    auto issue = [&](int kc) {
        int s = kc % NSTG;
        uint32_t st = sb + (uint32_t)s * STAGE;
        int k0 = kc * KC;
        mbar_expect(bars[s], STAGE);
        tma3d(st + O_A, &mA, k0, m0, src, bars[s]);
        tma2d(st + O_B, &mB, k0, n0, bars[s]);
    };
    if (tid == 0) { issue(0); issue(1); issue(2); }

    // warp tiling: 4 (m) x 2 (n); warp tile 32x64
    const int m_off = (w & 3) * 32;
    const int n_off = (w >> 2) * 64;
    const int par = l & 1;

    float acc[2][8][4];
    #pragma unroll
    for (int im = 0; im < 2; im++)
        #pragma unroll
        for (int jn = 0; jn < 8; jn++)
            #pragma unroll
            for (int q = 0; q < 4; q++) acc[im][jn][q] = 0.0f;

    // ldsm addresses — fp16 b16 fragment geometry (R7/R9-validated), SW128 128B rows
    auto a_addr = [&](uint32_t plane, int im, int ks) -> uint32_t {
        int row = m_off + im * 16 + (l & 15);
        uint32_t byte = ks * 32 + ((l >> 4) << 4);
        return plane + swz128((uint32_t)row * ROWB + byte);
    };
    auto b_addr = [&](uint32_t plane, int jn2, int ks) -> uint32_t {
        int row = n_off + jn2 * 16 + (l & 7) + ((l >> 4) << 3);
        uint32_t byte = ks * 32 + (((l >> 3) & 1) << 4);
        return plane + swz128((uint32_t)row * ROWB + byte);
    };

    // ---- mainloop: 3-stage TMA pipeline, one sync per chunk ----
    uint32_t wcnt[NSTG] = {0, 0, 0};
    for (int kc = 0; kc < NKC; kc++) {
        const int s = kc % NSTG;
        const uint32_t so = sb + (uint32_t)s * STAGE;
        mbar_wait(bars[s], wcnt[s] & 1);
        wcnt[s]++;
        #pragma unroll
        for (int ks = 0; ks < 4; ks++) {     // 4 x k16 per 64-element chunk
            uint32_t af[2][4], bf2[4][4];
            #pragma unroll
            for (int im = 0; im < 2; im++) ldsm_x4(a_addr(so + O_A, im, ks), af[im]);
            #pragma unroll
            for (int jn2 = 0; jn2 < 4; jn2++) ldsm_x4(b_addr(so + O_B, jn2, ks), bf2[jn2]);
            #pragma unroll
            for (int im = 0; im < 2; im++)
                #pragma unroll
                for (int jn = 0; jn < 8; jn++)
                    mma_f16(acc[im][jn], af[im], &bf2[jn >> 1][(jn & 1) * 2]);
        }
        __syncthreads();
        if (tid == 0 && kc + NSTG < NKC) issue(kc + NSTG);
    }

    // ---- fragment-direct epilogue + pred dot partials ----
    {
        float kpv[8][2], bpv[8][2], dwv[8];
        const int myq = (l & 3) >> 1;
        #pragma unroll
        for (int jn = 0; jn < 8; jn++) {
            #pragma unroll
            for (int q = 0; q < 2; q++) {
                int n = n0 + n_off + jn * 8 + (l & 3) * 2 + q;
                kpv[jn][q] = g_kp[n];
                bpv[jn][q] = g_bp[n];
            }
            dwv[jn] = dw[u0 + (n_off >> 2) + jn * 2 + myq];
        }
        #pragma unroll
        for (int im = 0; im < 2; im++) {
            #pragma unroll
            for (int half = 0; half < 2; half++) {
                int row = m0 + m_off + im * 16 + (l >> 2) + half * 8;
                float xr = (t == 0) ? 0.0f : g_x[row];
                float s = 0.0f;
                #pragma unroll
                for (int jn = 0; jn < 8; jn++) {
                    float zA = acc[im][jn][half * 2 + 0] + xr * kpv[jn][0] + bpv[jn][0];
                    float zB = acc[im][jn][half * 2 + 1] + xr * kpv[jn][1] + bpv[jn][1];
                    // even lane: i = sig(zA), f = sig(zB); odd lane: g = tanh(zA), o = sig(zB)
                    float vA = par ? tanhf_(zA) : sigf(zA);
                    float vB = sigf(zB);
                    int u = u0 + ((n_off + jn * 8 + (l & 3) * 2) >> 2);
                    size_t gi = (size_t)row * 1024 + u;
                    float gx = __shfl_xor_sync(0xFFFFFFFFu, vA, 1);  // even receives g
                    float cn = 0.0f;
                    if (!par) {
                        float co = g_c[gi];
                        cn = vB * co + vA * gx;       // f*c + i*g
                        g_c[gi] = cn;
                    }
                    float cnx = __shfl_xor_sync(0xFFFFFFFFu, cn, 1); // odd receives c_new
                    if (par) {
                        float hn = vB * tanhf_(cnx);  // o * tanh(c_new)
                        g_h[dst][gi] = __float2half_rn(hn);
                        s += hn * dwv[jn];
                    }
                }
                s += __shfl_xor_sync(0xFFFFFFFFu, s, 2);
                if ((l & 3) == 1)
                    g_xpart[row][nt * 2 + (n_off >> 6)] = s;
            }
        }
    }

    // ---- arrive; last tile of this m-block finishes pred + feedback ----
    __syncthreads();
    if (tid == 0) {
        __threadfence();
        int old = atomicAdd(&g_cnt[t][mt], 1);
        sflag = (old == NNT - 1) ? 1 : 0;
    }
    __syncthreads();
    if (sflag) {
        __threadfence();   // observe all tiles' xpart writes
        if (tid < 128) {
            float dbv = db[0];
            int row = m0 + tid;     // 128 rows
            const float4* xp4 = (const float4*)&g_xpart[row][0];
            float p = 0.0f;
            #pragma unroll
            for (int i = 0; i < 16; i++) {
                float4 v = xp4[i];
                p += v.x + v.y + v.z + v.w;
            }
            p += dbv;
            out[(size_t)row * TSTEPS + t] = p;
            g_x[row] = p;
        }
    }
}

// ---------------- host side ----------------
typedef CUresult (*PFN_tmap)(CUtensorMap*, CUtensorMapDataType, cuuint32_t, void*,
    const cuuint64_t*, const cuuint64_t*, const cuuint32_t*, const cuuint32_t*,
    CUtensorMapInterleave, CUtensorMapSwizzle, CUtensorMapL2promotion, CUtensorMapFloatOOBfill);

static void enc2d(PFN_tmap fn, CUtensorMap* m, void* base) {
    cuuint64_t dims[2]    = { 1024, 4096 };
    cuuint64_t strides[1] = { 2048 };          // row = 1024 fp16 = 2048 B
    cuuint32_t box[2]     = { KC, 128 };       // 64 fp16 = 128 B rows
    cuuint32_t es[2]      = { 1, 1 };
    fn(m, CU_TENSOR_MAP_DATA_TYPE_FLOAT16, 2, base, dims, strides, box, es,
       CU_TENSOR_MAP_INTERLEAVE_NONE, CU_TENSOR_MAP_SWIZZLE_128B,
       CU_TENSOR_MAP_L2_PROMOTION_L2_128B, CU_TENSOR_MAP_FLOAT_OOB_FILL_NONE);
}
static void enc3d(PFN_tmap fn, CUtensorMap* m, void* base) {
    cuuint64_t dims[3]    = { 1024, 4096, 2 };
    cuuint64_t strides[2] = { 2048, 4096ULL * 2048ULL };
    cuuint32_t box[3]     = { KC, 128, 1 };
    cuuint32_t es[3]      = { 1, 1, 1 };
    fn(m, CU_TENSOR_MAP_DATA_TYPE_FLOAT16, 3, base, dims, strides, box, es,
       CU_TENSOR_MAP_INTERLEAVE_NONE, CU_TENSOR_MAP_SWIZZLE_128B,
       CU_TENSOR_MAP_L2_PROMOTION_L2_128B, CU_TENSOR_MAP_FLOAT_OOB_FILL_NONE);
}

extern "C" void kernel_launch(void* const* d_in, const int* in_sizes, int n_in,
                              void* d_out, int out_size) {
    const float* features = (const float*)d_in[0];
    const float* kern     = (const float*)d_in[1];
    const float* W        = (const float*)d_in[2];
    const float* bias     = (const float*)d_in[3];
    const float* dw       = (const float*)d_in[4];
    const float* db       = (const float*)d_in[5];
    float* out = (float*)d_out;

    PFN_tmap enc = nullptr;
    {
        cudaDriverEntryPointQueryResult qr;
        void* fp = nullptr;
        cudaGetDriverEntryPointByVersion("cuTensorMapEncodeTiled", &fp, 12000,
                                         cudaEnableDefault, &qr);
        enc = (PFN_tmap)fp;
    }

    void *pH = nullptr, *pW = nullptr;
    cudaGetSymbolAddress(&pH, g_h);
    cudaGetSymbolAddress(&pW, g_W);

    CUtensorMap mA, mB;
    enc3d(enc, &mA, pH);
    enc2d(enc, &mB, pW);

    cudaFuncSetAttribute(step_kernel, cudaFuncAttributeMaxDynamicSharedMemorySize, SMEM_DYN);

    prep_w_kernel<<<dim3(32, 128, 4), dim3(32, 8)>>>(W);
    prep_small_kernel<<<16, 256>>>(kern, bias);
    init_hc_kernel<<<4096, 1024>>>(features);

    for (int t = 0; t < TSTEPS; t++) {
        step_kernel<<<NMT * NNT, 256, SMEM_DYN>>>(mA, mB, dw, db, out, t);
    }
}

// round 16
// speedup vs baseline: 2.0341x; 1.0064x over previous
#include <cuda_runtime.h>
#include <cuda.h>
#include <cuda_fp16.h>
#include <cstdint>
#include <cstddef>

// ---------------- problem constants ----------------
#define BATCH   4096
#define UNITS   1024
#define TSTEPS  128
#define BM      128            // batch rows per tile
#define BN      128            // z-cols per tile = 32 units * 4 gates
#define KC      64             // K fp16 elements per chunk (128B rows, SW128)
#define NKC     16             // chunks over K=1024
#define NKS     64             // total k16 steps (NKC*4)
#define NMT     32             // m tiles
#define NNT     32             // n tiles
#define ROWB    128            // smem row bytes
#define PL      (128 * ROWB)   // 16384 B per plane (A / B)
#define O_A     0
#define O_B     (PL)
#define STAGE   (2 * PL)       // 32768 B
#define NSTG    3
#define SMEM_DYN (NSTG * STAGE)   // 98304 B (2 CTAs/SM)
#define HN      (4096UL * 1024UL)

// ---------------- device-global state ----------------
__device__ __half g_h[2][HN];       // hidden state fp16 (ping/pong)
__device__ __half g_W[HN];          // permuted W fp16: [n=4u+g][k]
__device__ float  g_c[HN];          // cell state fp32, in place
__device__ float  g_kp[4 * UNITS];  // permuted input kernel
__device__ float  g_bp[4 * UNITS];  // permuted bias
__device__ float  g_x[BATCH];       // autoregressive feedback (pred of prev step)
__device__ int    g_cnt[TSTEPS][NMT];     // per (step, m-block) tile arrivals
__device__ float  g_xpart[BATCH][64];     // pred dot partials

// ---------------- PTX helpers ----------------
__device__ __forceinline__ uint32_t smem_u32(const void* p) {
    uint32_t a;
    asm("{ .reg .u64 t; cvta.to.shared.u64 t, %1; cvt.u32.u64 %0, t; }" : "=r"(a) : "l"(p));
    return a;
}
__device__ __forceinline__ void mbar_init(uint32_t a, uint32_t c) {
    asm volatile("mbarrier.init.shared.b64 [%0], %1;" :: "r"(a), "r"(c) : "memory");
}
__device__ __forceinline__ void mbar_expect(uint32_t a, uint32_t bytes) {
    asm volatile("mbarrier.arrive.expect_tx.shared.b64 _, [%0], %1;" :: "r"(a), "r"(bytes) : "memory");
}
__device__ __forceinline__ void mbar_wait(uint32_t a, uint32_t ph) {
    asm volatile(
        "{\n\t.reg .pred P;\n"
        "WL%=:\n\t"
        "mbarrier.try_wait.parity.acquire.cta.shared::cta.b64 P, [%0], %1, 0x989680;\n\t"
        "@P bra.uni WD%=;\n\t"
        "bra.uni WL%=;\n"
        "WD%=:\n\t}"
        :: "r"(a), "r"(ph) : "memory");
}
__device__ __forceinline__ void tma3d(uint32_t dst, const CUtensorMap* m, int x, int y, int z, uint32_t bar) {
    asm volatile(
        "cp.async.bulk.tensor.3d.shared::cta.global.tile.mbarrier::complete_tx::bytes "
        "[%0], [%1, {%2, %3, %4}], [%5];"
        :: "r"(dst), "l"(m), "r"(x), "r"(y), "r"(z), "r"(bar) : "memory");
}
__device__ __forceinline__ void tma2d(uint32_t dst, const CUtensorMap* m, int x, int y, uint32_t bar) {
    asm volatile(
        "cp.async.bulk.tensor.2d.shared::cta.global.tile.mbarrier::complete_tx::bytes "
        "[%0], [%1, {%2, %3}], [%4];"
        :: "r"(dst), "l"(m), "r"(x), "r"(y), "r"(bar) : "memory");
}
__device__ __forceinline__ void ldsm_x4(uint32_t addr, uint32_t* r) {
    asm volatile("ldmatrix.sync.aligned.m8n8.x4.shared.b16 {%0,%1,%2,%3}, [%4];"
                 : "=r"(r[0]), "=r"(r[1]), "=r"(r[2]), "=r"(r[3]) : "r"(addr));
}
__device__ __forceinline__ void mma_f16(float* d, const uint32_t* a, const uint32_t* b) {
    asm volatile(
        "mma.sync.aligned.m16n8k16.row.col.f32.f16.f16.f32 "
        "{%0,%1,%2,%3}, {%4,%5,%6,%7}, {%8,%9}, {%0,%1,%2,%3};"
        : "+f"(d[0]), "+f"(d[1]), "+f"(d[2]), "+f"(d[3])
        : "r"(a[0]), "r"(a[1]), "r"(a[2]), "r"(a[3]), "r"(b[0]), "r"(b[1]));
}
__device__ __forceinline__ float sigf(float x) {
    return __fdividef(1.0f, 1.0f + __expf(-x));
}
__device__ __forceinline__ float tanhf_(float x) {
    return __fdividef(2.0f, 1.0f + __expf(-2.0f * x)) - 1.0f;
}
__device__ __forceinline__ uint32_t swz128(uint32_t off) {
    return off ^ ((off >> 3) & 0x70);
}

// ---------------- prep kernels ----------------
__global__ void prep_w_kernel(const float* __restrict__ W) {
    int u = blockIdx.x * 32 + threadIdx.x;
    int k = blockIdx.y * 8 + threadIdx.y;
    int g = blockIdx.z;
    float v = W[(size_t)k * 4096 + g * 1024 + u];
    g_W[((size_t)(4 * u + g)) * 1024 + k] = __float2half_rn(v);
}

__global__ void prep_small_kernel(const float* __restrict__ kern, const float* __restrict__ bias) {
    int idx = blockIdx.x * 256 + threadIdx.x;   // 0..4095
    int g = idx & 3, u = idx >> 2;
    int c = g * 1024 + u;
    g_kp[idx] = kern[c];
    g_bp[idx] = bias[c];
    if (idx < TSTEPS * NMT) ((int*)g_cnt)[idx] = 0;
}

__global__ void init_hc_kernel(const float* __restrict__ feat) {
    size_t idx = (size_t)blockIdx.x * 1024 + threadIdx.x;
    int b = blockIdx.x, u = threadIdx.x;
    float v = feat[(size_t)b * 512 + (u & 511)];
    g_h[0][idx] = __float2half_rn(v);
    g_c[idx] = v;
}

// ---------------- fused LSTM step (fp16, 2-deep fragment double-buffer) ----------------
__global__ void __launch_bounds__(256, 2)
step_kernel(const __grid_constant__ CUtensorMap mA,
            const __grid_constant__ CUtensorMap mB,
            const float* __restrict__ dw,
            const float* __restrict__ db,
            float* __restrict__ out,
            int t)
{
    extern __shared__ __align__(1024) char sm[];
    __shared__ uint64_t barmem[NSTG];
    __shared__ int sflag;

    const int tid = threadIdx.x;
    const int w = tid >> 5, l = tid & 31;
    const int src = t & 1;
    const int dst = src ^ 1;
    const int mt = blockIdx.x & 31, nt = blockIdx.x >> 5;
    const int m0 = mt << 7;      // batch row base
    const int n0 = nt << 7;      // z col base (128 cols)
    const int u0 = nt << 5;      // unit base (32 units)

    const uint32_t sb = smem_u32(sm);
    uint32_t bars[NSTG];
    #pragma unroll
    for (int s = 0; s < NSTG; s++) bars[s] = smem_u32(&barmem[s]);

    if (tid == 0) {
        #pragma unroll
        for (int s = 0; s < NSTG; s++) mbar_init(bars[s], 1);
        asm volatile("fence.proxy.async.shared::cta;" ::: "memory");
    }
    __syncthreads();

    // producer: issue chunk kc into stage kc%3 (tid 0 only)
    auto issue = [&](int kc) {
        int s = kc % NSTG;
        uint32_t st = sb + (uint32_t)s * STAGE;
        int k0 = kc * KC;
        mbar_expect(bars[s], STAGE);
        tma3d(st + O_A, &mA, k0, m0, src, bars[s]);
        tma2d(st + O_B, &mB, k0, n0, bars[s]);
    };
    if (tid == 0) { issue(0); issue(1); issue(2); }

    // warp tiling: 4 (m) x 2 (n); warp tile 32x64
    const int m_off = (w & 3) * 32;
    const int n_off = (w >> 2) * 64;
    const int par = l & 1;

    float acc[2][8][4];
    #pragma unroll
    for (int im = 0; im < 2; im++)
        #pragma unroll
        for (int jn = 0; jn < 8; jn++)
            #pragma unroll
            for (int q = 0; q < 4; q++) acc[im][jn][q] = 0.0f;

    // ldsm addresses — fp16 b16 fragment geometry, SW128 128B rows
    auto a_addr = [&](uint32_t plane, int im, int ks) -> uint32_t {
        int row = m_off + im * 16 + (l & 15);
        uint32_t byte = ks * 32 + ((l >> 4) << 4);
        return plane + swz128((uint32_t)row * ROWB + byte);
    };
    auto b_addr = [&](uint32_t plane, int jn2, int ks) -> uint32_t {
        int row = n_off + jn2 * 16 + (l & 7) + ((l >> 4) << 3);
        uint32_t byte = ks * 32 + (((l >> 3) & 1) << 4);
        return plane + swz128((uint32_t)row * ROWB + byte);
    };

    // fragment buffers: 2-deep double buffer (static indices only)
    uint32_t fa[2][8], fb[2][16];
    uint32_t wcnt[NSTG] = {0, 0, 0};

    auto load_frags = [&](uint32_t* afb, uint32_t* bfb, int kstep) {
        uint32_t so = sb + (uint32_t)((kstep >> 2) % NSTG) * STAGE;
        int ks = kstep & 3;
        ldsm_x4(a_addr(so + O_A, 0, ks), afb + 0);
        ldsm_x4(a_addr(so + O_A, 1, ks), afb + 4);
        #pragma unroll
        for (int jn2 = 0; jn2 < 4; jn2++)
            ldsm_x4(b_addr(so + O_B, jn2, ks), bfb + 4 * jn2);
    };
    auto do_mma = [&](const uint32_t* afb, const uint32_t* bfb) {
        #pragma unroll
        for (int im = 0; im < 2; im++)
            #pragma unroll
            for (int jn = 0; jn < 8; jn++)
                mma_f16(acc[im][jn], afb + 4 * im, bfb + (jn >> 1) * 4 + (jn & 1) * 2);
    };
    // crossing into chunk c = kn>>2: release old stage, refill, wait new stage
    auto cross = [&](int kn) {
        __syncthreads();                       // all reads of previous stage done
        int c = kn >> 2;
        if (tid == 0 && c + 2 < NKC) issue(c + 2);
        int s = c % NSTG;
        mbar_wait(bars[s], wcnt[s] & 1);
        wcnt[s]++;
    };

    // ---- mainloop: flat 64 k16-steps, fragments double-buffered ----
    mbar_wait(bars[0], 0); wcnt[0] = 1;
    load_frags(fa[0], fb[0], 0);
    for (int kk = 0; kk < 32; kk++) {
        int k0 = 2 * kk;
        // k0 and k0+1 are always in the same chunk (k0 even)
        load_frags(fa[1], fb[1], k0 + 1);
        do_mma(fa[0], fb[0]);
        int kn = k0 + 2;
        if (kn < NKS) {
            if ((kn & 3) == 0) cross(kn);
            load_frags(fa[0], fb[0], kn);
        }
        do_mma(fa[1], fb[1]);
    }
    __syncthreads();

    // ---- fragment-direct epilogue + pred dot partials ----
    {
        float kpv[8][2], bpv[8][2], dwv[8];
        const int myq = (l & 3) >> 1;
        #pragma unroll
        for (int jn = 0; jn < 8; jn++) {
            #pragma unroll
            for (int q = 0; q < 2; q++) {
                int n = n0 + n_off + jn * 8 + (l & 3) * 2 + q;
                kpv[jn][q] = g_kp[n];
                bpv[jn][q] = g_bp[n];
            }
            dwv[jn] = dw[u0 + (n_off >> 2) + jn * 2 + myq];
        }
        #pragma unroll
        for (int im = 0; im < 2; im++) {
            #pragma unroll
            for (int half = 0; half < 2; half++) {
                int row = m0 + m_off + im * 16 + (l >> 2) + half * 8;
                float xr = (t == 0) ? 0.0f : g_x[row];
                float s = 0.0f;
                #pragma unroll
                for (int jn = 0; jn < 8; jn++) {
                    float zA = acc[im][jn][half * 2 + 0] + xr * kpv[jn][0] + bpv[jn][0];
                    float zB = acc[im][jn][half * 2 + 1] + xr * kpv[jn][1] + bpv[jn][1];
                    // even lane: i = sig(zA), f = sig(zB); odd lane: g = tanh(zA), o = sig(zB)
                    float vA = par ? tanhf_(zA) : sigf(zA);
                    float vB = sigf(zB);
                    int u = u0 + ((n_off + jn * 8 + (l & 3) * 2) >> 2);
                    size_t gi = (size_t)row * 1024 + u;
                    float gx = __shfl_xor_sync(0xFFFFFFFFu, vA, 1);  // even receives g
                    float cn = 0.0f;
                    if (!par) {
                        float co = g_c[gi];
                        cn = vB * co + vA * gx;       // f*c + i*g
                        g_c[gi] = cn;
                    }
                    float cnx = __shfl_xor_sync(0xFFFFFFFFu, cn, 1); // odd receives c_new
                    if (par) {
                        float hn = vB * tanhf_(cnx);  // o * tanh(c_new)
                        g_h[dst][gi] = __float2half_rn(hn);
                        s += hn * dwv[jn];
                    }
                }
                s += __shfl_xor_sync(0xFFFFFFFFu, s, 2);
                if ((l & 3) == 1)
                    g_xpart[row][nt * 2 + (n_off >> 6)] = s;
            }
        }
    }

    // ---- arrive; last tile of this m-block finishes pred + feedback ----
    __syncthreads();
    if (tid == 0) {
        __threadfence();
        int old = atomicAdd(&g_cnt[t][mt], 1);
        sflag = (old == NNT - 1) ? 1 : 0;
    }
    __syncthreads();
    if (sflag) {
        __threadfence();   // observe all tiles' xpart writes
        if (tid < 128) {
            float dbv = db[0];
            int row = m0 + tid;     // 128 rows
            const float4* xp4 = (const float4*)&g_xpart[row][0];
            float p = 0.0f;
            #pragma unroll
            for (int i = 0; i < 16; i++) {
                float4 v = xp4[i];
                p += v.x + v.y + v.z + v.w;
            }
            p += dbv;
            out[(size_t)row * TSTEPS + t] = p;
            g_x[row] = p;
        }
    }
}

// ---------------- host side ----------------
typedef CUresult (*PFN_tmap)(CUtensorMap*, CUtensorMapDataType, cuuint32_t, void*,
    const cuuint64_t*, const cuuint64_t*, const cuuint32_t*, const cuuint32_t*,
    CUtensorMapInterleave, CUtensorMapSwizzle, CUtensorMapL2promotion, CUtensorMapFloatOOBfill);

static void enc2d(PFN_tmap fn, CUtensorMap* m, void* base) {
    cuuint64_t dims[2]    = { 1024, 4096 };
    cuuint64_t strides[1] = { 2048 };          // row = 1024 fp16 = 2048 B
    cuuint32_t box[2]     = { KC, 128 };       // 64 fp16 = 128 B rows
    cuuint32_t es[2]      = { 1, 1 };
    fn(m, CU_TENSOR_MAP_DATA_TYPE_FLOAT16, 2, base, dims, strides, box, es,
       CU_TENSOR_MAP_INTERLEAVE_NONE, CU_TENSOR_MAP_SWIZZLE_128B,
       CU_TENSOR_MAP_L2_PROMOTION_L2_128B, CU_TENSOR_MAP_FLOAT_OOB_FILL_NONE);
}
static void enc3d(PFN_tmap fn, CUtensorMap* m, void* base) {
    cuuint64_t dims[3]    = { 1024, 4096, 2 };
    cuuint64_t strides[2] = { 2048, 4096ULL * 2048ULL };
    cuuint32_t box[3]     = { KC, 128, 1 };
    cuuint32_t es[3]      = { 1, 1, 1 };
    fn(m, CU_TENSOR_MAP_DATA_TYPE_FLOAT16, 3, base, dims, strides, box, es,
       CU_TENSOR_MAP_INTERLEAVE_NONE, CU_TENSOR_MAP_SWIZZLE_128B,
       CU_TENSOR_MAP_L2_PROMOTION_L2_128B, CU_TENSOR_MAP_FLOAT_OOB_FILL_NONE);
}

extern "C" void kernel_launch(void* const* d_in, const int* in_sizes, int n_in,
                              void* d_out, int out_size) {
    const float* features = (const float*)d_in[0];
    const float* kern     = (const float*)d_in[1];
    const float* W        = (const float*)d_in[2];
    const float* bias     = (const float*)d_in[3];
    const float* dw       = (const float*)d_in[4];
    const float* db       = (const float*)d_in[5];
    float* out = (float*)d_out;

    PFN_tmap enc = nullptr;
    {
        cudaDriverEntryPointQueryResult qr;
        void* fp = nullptr;
        cudaGetDriverEntryPointByVersion("cuTensorMapEncodeTiled", &fp, 12000,
                                         cudaEnableDefault, &qr);
        enc = (PFN_tmap)fp;
    }

    void *pH = nullptr, *pW = nullptr;
    cudaGetSymbolAddress(&pH, g_h);
    cudaGetSymbolAddress(&pW, g_W);

    CUtensorMap mA, mB;
    enc3d(enc, &mA, pH);
    enc2d(enc, &mB, pW);

    cudaFuncSetAttribute(step_kernel, cudaFuncAttributeMaxDynamicSharedMemorySize, SMEM_DYN);

    prep_w_kernel<<<dim3(32, 128, 4), dim3(32, 8)>>>(W);
    prep_small_kernel<<<16, 256>>>(kern, bias);
    init_hc_kernel<<<4096, 1024>>>(features);

    for (int t = 0; t < TSTEPS; t++) {
        step_kernel<<<NMT * NNT, 256, SMEM_DYN>>>(mA, mB, dw, db, out, t);
    }
}